// round 4
// baseline (speedup 1.0000x reference)
#include <cuda_runtime.h>
#include <math.h>

#define Nn   50000
#define Ee   1600000
#define Dh   64
#define Din  128
#define Gg   64
#define NCLS 10
#define NBLK 49              // ceil(Nn/1024)
#define GEMM1_BLOCKS 782     // ceil(Nn/64)
#define SCAT_BLOCKS  6250    // ceil(Ee/256)

// ---------------- scratch (device globals; referenced ONLY in device code) ----------
__device__ float g_xl[Nn * Dh];      // pair-interleaved: slot 2l,2l+1 = dims l, l+32
__device__ float g_xr[Nn * Dh];
__device__ float g_h [Nn * Dh];
__device__ int   g_deg[Nn];
__device__ int   g_indptr[Nn + 1];
__device__ int   g_wpos[Nn];
__device__ int2  g_csr[Ee];          // {src, attr-as-int}
__device__ float g_attrsum;
__device__ float g_pooled[Gg * Dh];
__device__ int   g_cnt[Gg];
__device__ int   g_bsum[64], g_boff[64];
// pre-permuted weights (pair-interleaved columns; layer-2 rows in storage order)
__device__ float g_pwl1[Din * Dh], g_pwr1[Din * Dh];
__device__ float g_pwl2[Dh * Dh],  g_pwr2[Dh * Dh];

// ---------------- f32x2 helpers ----------------
__device__ __forceinline__ unsigned long long pack2(float x, float y) {
    unsigned long long r;
    asm("mov.b64 %0, {%1, %2};" : "=l"(r) : "f"(x), "f"(y));
    return r;
}
__device__ __forceinline__ void fma2(unsigned long long& d, unsigned long long a,
                                     unsigned long long b) {
    asm("fma.rn.f32x2 %0, %1, %2, %3;" : "=l"(d) : "l"(a), "l"(b), "l"(d));
}
__device__ __forceinline__ float2 unpack2(unsigned long long v) {
    float2 r;
    asm("mov.b64 {%0, %1}, %2;" : "=f"(r.x), "=f"(r.y) : "l"(v));
    return r;
}

// ---------------- init: zero per-call scratch + permute weights ----------------
__global__ void init_kernel(const float* __restrict__ Wl1, const float* __restrict__ Wr1,
                            const float* __restrict__ Wl2, const float* __restrict__ Wr2) {
    int b = blockIdx.x, t = threadIdx.x;
    if (b < 196) {
        int i = b * 256 + t;
        if (i < Nn) g_deg[i] = 0;
        if (i < Gg * Dh) g_pooled[i] = 0.f;
        if (i < Gg) g_cnt[i] = 0;
        if (i == 0) g_attrsum = 0.f;
    } else {
        int idx = (b - 196) * 256 + t;
        if (idx < Din * Dh) {                      // layer-1 weights [128][64]
            int k = idx >> 6, d = idx & 63;
            int st = 2 * (d & 31) + (d >> 5);
            g_pwl1[k * 64 + st] = Wl1[idx];
            g_pwr1[k * 64 + st] = Wr1[idx];
        } else if (idx < Din * Dh + Dh * Dh) {     // layer-2 weights [64][64]
            int j = idx - Din * Dh;
            int k = j >> 6, d = j & 63;
            int srow = 2 * (k & 31) + (k >> 5);    // input rows in storage order
            int st   = 2 * (d & 31) + (d >> 5);
            g_pwl2[srow * 64 + st] = Wl2[j];
            g_pwr2[srow * 64 + st] = Wr2[j];
        }
    }
}

// ---------------- degree count + edge_attr sum ----------------
__global__ void count_kernel(const int* __restrict__ dst, const float* __restrict__ attr) {
    int e = blockIdx.x * blockDim.x + threadIdx.x;
    float v = 0.f;
    if (e < Ee) {
        atomicAdd(&g_deg[dst[e]], 1);
        v = attr[e];
    }
    #pragma unroll
    for (int o = 16; o; o >>= 1) v += __shfl_xor_sync(0xffffffffu, v, o);
    __shared__ float red[8];
    int lane = threadIdx.x & 31, wid = threadIdx.x >> 5;
    if (lane == 0) red[wid] = v;
    __syncthreads();
    if (threadIdx.x < 8) {
        float w = red[threadIdx.x];
        #pragma unroll
        for (int o = 4; o; o >>= 1) w += __shfl_xor_sync(0xffu, w, o);
        if (threadIdx.x == 0) atomicAdd(&g_attrsum, w);
    }
}

// ---------------- parallel scan: per-block local scan ----------------
__global__ void scan1_kernel() {
    __shared__ int wsum[32];
    int b = blockIdx.x, tid = threadIdx.x, lane = tid & 31, wid = tid >> 5;
    int i = b * 1024 + tid;
    int v = (i < Nn) ? g_deg[i] : 0;
    int x = v;
    #pragma unroll
    for (int o = 1; o < 32; o <<= 1) {
        int y = __shfl_up_sync(0xffffffffu, x, o);
        if (lane >= o) x += y;
    }
    if (lane == 31) wsum[wid] = x;
    __syncthreads();
    if (wid == 0) {
        int w = wsum[lane];
        #pragma unroll
        for (int o = 1; o < 32; o <<= 1) {
            int y = __shfl_up_sync(0xffffffffu, w, o);
            if (lane >= o) w += y;
        }
        wsum[lane] = w;
    }
    __syncthreads();
    int excl = (wid ? wsum[wid - 1] : 0) + x - v;
    if (i < Nn) g_indptr[i] = excl;
    if (tid == 0) g_bsum[b] = wsum[31];
}

// ---------------- scan block sums (one warp, 2 chunks of 32) ----------------
__global__ void scan2_kernel() {
    int lane = threadIdx.x;   // 32 threads
    int v0 = (lane < NBLK) ? g_bsum[lane] : 0;
    int v1 = (lane + 32 < NBLK) ? g_bsum[lane + 32] : 0;
    int x = v0;
    #pragma unroll
    for (int o = 1; o < 32; o <<= 1) {
        int y = __shfl_up_sync(0xffffffffu, x, o);
        if (lane >= o) x += y;
    }
    int tot0 = __shfl_sync(0xffffffffu, x, 31);
    int z = v1;
    #pragma unroll
    for (int o = 1; o < 32; o <<= 1) {
        int y = __shfl_up_sync(0xffffffffu, z, o);
        if (lane >= o) z += y;
    }
    if (lane < NBLK) g_boff[lane] = x - v0;
    if (lane + 32 < NBLK) g_boff[lane + 32] = tot0 + z - v1;
    if (lane == 31) g_indptr[Nn] = tot0 + z;
}

// ---------------- add block offsets; init write cursors ----------------
__global__ void scan3_kernel() {
    int b = blockIdx.x;
    int i = b * 1024 + threadIdx.x;
    if (i < Nn) {
        int v = g_indptr[i] + g_boff[b];
        g_indptr[i] = v;
        g_wpos[i]   = v;
    }
}

// ---------------- dual GEMM body (no smem, f32x2, pair-interleaved output) ----------
template <int K, bool USE_GH>
__device__ __forceinline__ void gemm_body(const float* __restrict__ X,
                                          const float* __restrict__ pWl,
                                          const float* __restrict__ pWr,
                                          const float* __restrict__ bl,
                                          const float* __restrict__ br,
                                          int bid, int tid) {
    int warp = tid >> 5, lane = tid & 31;
    int row0 = bid * 64 + warp * 8;
    const float* __restrict__ IN = USE_GH ? g_h : X;
    const float2* __restrict__ wl2p = (const float2*)pWl;
    const float2* __restrict__ wr2p = (const float2*)pWr;
    unsigned long long aL[8], aR[8];
    #pragma unroll
    for (int j = 0; j < 8; j++) { aL[j] = 0ull; aR[j] = 0ull; }
    for (int k0 = 0; k0 < K; k0 += 4) {
        unsigned long long wl[4], wr[4];
        #pragma unroll
        for (int u = 0; u < 4; u++) {
            float2 a = wl2p[(k0 + u) * 32 + lane]; wl[u] = pack2(a.x, a.y);
            float2 b = wr2p[(k0 + u) * 32 + lane]; wr[u] = pack2(b.x, b.y);
        }
        #pragma unroll
        for (int j = 0; j < 8; j++) {
            int gr = row0 + j;
            float4 xv = (gr < Nn) ? *(const float4*)&IN[gr * K + k0]
                                  : make_float4(0.f, 0.f, 0.f, 0.f);
            unsigned long long x0 = pack2(xv.x, xv.x), x1 = pack2(xv.y, xv.y);
            unsigned long long x2 = pack2(xv.z, xv.z), x3 = pack2(xv.w, xv.w);
            fma2(aL[j], x0, wl[0]); fma2(aR[j], x0, wr[0]);
            fma2(aL[j], x1, wl[1]); fma2(aR[j], x1, wr[1]);
            fma2(aL[j], x2, wl[2]); fma2(aR[j], x2, wr[2]);
            fma2(aL[j], x3, wl[3]); fma2(aR[j], x3, wr[3]);
        }
    }
    float b0 = bl[lane], b1 = bl[lane + 32];
    float c0 = br[lane], c1 = br[lane + 32];
    #pragma unroll
    for (int j = 0; j < 8; j++) {
        int gr = row0 + j;
        if (gr < Nn) {
            float2 l = unpack2(aL[j]); l.x += b0; l.y += b1;
            float2 r = unpack2(aR[j]); r.x += c0; r.y += c1;
            *(float2*)&g_xl[gr * 64 + 2 * lane] = l;
            *(float2*)&g_xr[gr * 64 + 2 * lane] = r;
        }
    }
}

// ---------------- merged launch: gemm1 (FMA-bound) || scatter (L2-bound) -----------
__global__ void gemm1_scatter_kernel(const float* __restrict__ X,
                                     const float* __restrict__ bl1,
                                     const float* __restrict__ br1,
                                     const int* __restrict__ src,
                                     const int* __restrict__ dst,
                                     const float* __restrict__ attr) {
    if (blockIdx.x < GEMM1_BLOCKS) {
        gemm_body<Din, false>(X, g_pwl1, g_pwr1, bl1, br1, blockIdx.x, threadIdx.x);
    } else {
        int e = (blockIdx.x - GEMM1_BLOCKS) * 256 + threadIdx.x;
        if (e < Ee) {
            int d = dst[e];
            int p = atomicAdd(&g_wpos[d], 1);
            g_csr[p] = make_int2(src[e], __float_as_int(attr[e]));
        }
    }
}

__global__ void gemm2_kernel(const float* __restrict__ bl2, const float* __restrict__ br2) {
    gemm_body<Dh, true>(nullptr, g_pwl2, g_pwr2, bl2, br2, blockIdx.x, threadIdx.x);
}

// ---------------- GATv2: warp per node, online softmax, float2 gathers -------------
__global__ void gat_kernel(const float* __restrict__ We, const float* __restrict__ att,
                           const float* __restrict__ bias) {
    int i = (blockIdx.x * blockDim.x + threadIdx.x) >> 5;
    int lane = threadIdx.x & 31;
    if (i >= Nn) return;
    float2 xr2 = *(const float2*)&g_xr[i * 64 + 2 * lane];
    float we0 = We[lane],  we1 = We[lane + 32];
    float at0 = att[lane], at1 = att[lane + 32];
    float mean_attr = g_attrsum * (1.0f / Ee);
    int beg = g_indptr[i], end = g_indptr[i + 1];
    float m = -INFINITY, s = 0.f, a0 = 0.f, a1 = 0.f;
    for (int e = beg; e <= end; ++e) {          // e == end -> self loop
        int src; float attr;
        if (e < end) { int2 ea = g_csr[e]; src = ea.x; attr = __int_as_float(ea.y); }
        else         { src = i;            attr = mean_attr; }
        float2 xl2 = *(const float2*)&g_xl[src * 64 + 2 * lane];
        float t0 = xl2.x + xr2.x + attr * we0;
        float t1 = xl2.y + xr2.y + attr * we1;
        t0 = fmaxf(t0, 0.2f * t0);              // leaky relu (slope 0.2 < 1)
        t1 = fmaxf(t1, 0.2f * t1);
        float p = fmaf(t0, at0, t1 * at1);
        #pragma unroll
        for (int o = 16; o; o >>= 1) p += __shfl_xor_sync(0xffffffffu, p, o);
        if (p > m) {                            // warp-uniform branch
            float sc = __expf(m - p);           // exp(-inf)=0 on first edge
            s  = fmaf(s,  sc, 1.f);
            a0 = fmaf(a0, sc, xl2.x);
            a1 = fmaf(a1, sc, xl2.y);
            m = p;
        } else {
            float z = __expf(p - m);
            s += z;
            a0 = fmaf(z, xl2.x, a0);
            a1 = fmaf(z, xl2.y, a1);
        }
    }
    float inv = 1.f / (s + 1e-16f);
    float o0 = fmaf(a0, inv, bias[lane]);
    float o1 = fmaf(a1, inv, bias[lane + 32]);
    o0 = o0 > 0.f ? o0 : expm1f(o0);            // ELU
    o1 = o1 > 0.f ? o1 : expm1f(o1);
    *(float2*)&g_h[i * 64 + 2 * lane] = make_float2(o0, o1);
}

// ---------------- mean pool per graph (batch sorted; storage-order dims) -----------
__global__ void pool_kernel(const int* __restrict__ batch) {
    int d = threadIdx.x;                 // 64 threads = 64 storage slots
    int n0 = blockIdx.x * 256;
    int n1 = n0 + 256; if (n1 > Nn) n1 = Nn;
    float acc = 0.f; int curg = -1; int c = 0;
    for (int n = n0; n < n1; ++n) {
        int g = batch[n];
        if (g != curg) {
            if (curg >= 0) {
                atomicAdd(&g_pooled[curg * Dh + d], acc);
                if (d == 0) atomicAdd(&g_cnt[curg], c);
            }
            curg = g; acc = 0.f; c = 0;
        }
        acc += g_h[n * Dh + d];
        ++c;
    }
    if (curg >= 0) {
        atomicAdd(&g_pooled[curg * Dh + d], acc);
        if (d == 0) atomicAdd(&g_cnt[curg], c);
    }
}

// ---------------- classifier (un-permutes storage -> dim) ----------------
__global__ void cls_kernel(const float* __restrict__ Wc, const float* __restrict__ bc,
                           float* __restrict__ out) {
    int t = threadIdx.x;                 // 640 threads
    int g = t / NCLS, c = t - g * NCLS;
    float invc = 1.f / fmaxf((float)g_cnt[g], 1.f);
    float acc = bc[c];
    #pragma unroll 8
    for (int s = 0; s < Dh; ++s) {
        int d = (s >> 1) + ((s & 1) << 5);     // storage slot -> true dim
        acc += g_pooled[g * Dh + s] * invc * Wc[d * NCLS + c];
    }
    out[t] = acc;
}

// ---------------- launch ----------------
extern "C" void kernel_launch(void* const* d_in, const int* in_sizes, int n_in,
                              void* d_out, int out_size) {
    const float* x    = (const float*)d_in[0];
    const int*   ei   = (const int*)  d_in[1];
    const float* eatt = (const float*)d_in[2];
    const int*   batch= (const int*)  d_in[3];
    const float* Wl1 = (const float*)d_in[4],  *bl1 = (const float*)d_in[5];
    const float* Wr1 = (const float*)d_in[6],  *br1 = (const float*)d_in[7];
    const float* We1 = (const float*)d_in[8],  *att1= (const float*)d_in[9];
    const float* b1  = (const float*)d_in[10];
    const float* Wl2 = (const float*)d_in[11], *bl2 = (const float*)d_in[12];
    const float* Wr2 = (const float*)d_in[13], *br2 = (const float*)d_in[14];
    const float* We2 = (const float*)d_in[15], *att2= (const float*)d_in[16];
    const float* b2  = (const float*)d_in[17];
    const float* Wc  = (const float*)d_in[18], *bc  = (const float*)d_in[19];
    float* out = (float*)d_out;

    const int* src = ei;
    const int* dst = ei + Ee;

    init_kernel<<<196 + 48, 256>>>(Wl1, Wr1, Wl2, Wr2);
    count_kernel<<<SCAT_BLOCKS, 256>>>(dst, eatt);
    scan1_kernel<<<NBLK, 1024>>>();
    scan2_kernel<<<1, 32>>>();
    scan3_kernel<<<NBLK, 1024>>>();
    gemm1_scatter_kernel<<<GEMM1_BLOCKS + SCAT_BLOCKS, 256>>>(x, bl1, br1, src, dst, eatt);
    gat_kernel<<<(Nn * 32 + 255) / 256, 256>>>(We1, att1, b1);
    gemm2_kernel<<<GEMM1_BLOCKS, 256>>>(bl2, br2);
    gat_kernel<<<(Nn * 32 + 255) / 256, 256>>>(We2, att2, b2);
    pool_kernel<<<(Nn + 255) / 256, 64>>>(batch);
    cls_kernel<<<1, Gg * NCLS>>>(Wc, bc, out);
}